// round 13
// baseline (speedup 1.0000x reference)
#include <cuda_runtime.h>
#include <cuda_fp16.h>
#include <cstdint>

#define BATCH 16
#define CIN   128
#define COUT  128
#define HH    64
#define WW    64

// ---------------------------------------------------------------------------
// Scratch (device globals: allocation-free rule)
// ---------------------------------------------------------------------------
__device__ float g_offmask[(size_t)BATCH*27*HH*WW]; // [b][27][h][w]
// Main-conv weights fp16, layout [stage s = half*9 + tap][o:128][k:64]
__device__ __half g_wA[18*128*64];
// Offset/mask-conv weights fp16, layout [stage][o:32 (27 used)][k:64]
__device__ __half g_wOM[18*32*64];

typedef unsigned long long ull;

// ---------------------------------------------------------------------------
// Helpers
// ---------------------------------------------------------------------------
__device__ __forceinline__ uint32_t smem_u32(const void* p){
    uint32_t a;
    asm("{ .reg .u64 t; cvta.to.shared.u64 t, %1; cvt.u32.u64 %0, t; }" : "=r"(a) : "l"(p));
    return a;
}

#define LDMX4(r, addr) \
    asm volatile("ldmatrix.sync.aligned.m8n8.x4.shared.b16 {%0,%1,%2,%3}, [%4];" \
        : "=r"((r)[0]), "=r"((r)[1]), "=r"((r)[2]), "=r"((r)[3]) : "r"(addr))

#define MMA16816(d, a0, a1, a2, a3, b0, b1) \
    asm volatile("mma.sync.aligned.m16n8k16.row.col.f32.f16.f16.f32 " \
        "{%0,%1,%2,%3}, {%4,%5,%6,%7}, {%8,%9}, {%0,%1,%2,%3};" \
        : "+f"((d)[0]), "+f"((d)[1]), "+f"((d)[2]), "+f"((d)[3]) \
        : "r"(a0), "r"(a1), "r"(a2), "r"(a3), "r"(b0), "r"(b1))

#define CP_ASYNC16(dst, src) \
    asm volatile("cp.async.ca.shared.global [%0], [%1], 16;" :: "r"(dst), "l"(src))
#define CP_COMMIT()  asm volatile("cp.async.commit_group;" ::: "memory")
#define CP_WAIT0()   asm volatile("cp.async.wait_group 0;" ::: "memory")

// Named-barrier producer/consumer sync, parameterized participant count
#define BAR_SYNC(id, cnt)   asm volatile("bar.sync %0, %1;"   :: "r"(id), "r"(cnt) : "memory")
#define BAR_ARRIVE(id, cnt) asm volatile("bar.arrive %0, %1;" :: "r"(id), "r"(cnt) : "memory")

__device__ __forceinline__ uint32_t pack_h2(float v0, float v1){
    __half h0 = __float2half_rn(v0);
    __half h1 = __float2half_rn(v1);
    return ((uint32_t)__half_as_ushort(h1) << 16) | __half_as_ushort(h0);
}

// ---------------------------------------------------------------------------
// Kernel 0: prep fp16 weight tiles for both GEMMs
// ---------------------------------------------------------------------------
__global__ void prep_w_kernel(const float* __restrict__ w_conv,
                              const float* __restrict__ w_off,
                              const float* __restrict__ w_mask){
    int i = blockIdx.x * blockDim.x + threadIdx.x;
    if (i < 18*128*64){
        int n = i / (128*128);
        int o = (i >> 7) & 127;
        int c = i & 127;
        float w = w_conv[((size_t)o*128 + c)*9 + n];
        int s = (c >> 6)*9 + n;
        size_t di = ((size_t)s*128 + o)*64 + (c & 63);
        g_wA[di] = __float2half_rn(w);
    }
    if (i < 18*32*64){
        int s  = i >> 11;
        int o  = (i >> 6) & 31;
        int cl = i & 63;
        int half = s / 9, n = s - half*9;
        int c = half*64 + cl;
        float w = 0.f;
        if (o < 18)      w = w_off [((size_t)o*128 + c)*9 + n];
        else if (o < 27) w = w_mask[((size_t)(o-18)*128 + c)*9 + n];
        g_wOM[i] = __float2half_rn(w);
    }
}

// ---------------------------------------------------------------------------
// Kernel 1: offset+mask conv as fp16 MMA, warp-specialized (proven R9 version)
// Block = (b, 2 h-rows): D[32 oc][128 px], K=1152 in 18 half-major stages.
// ---------------------------------------------------------------------------
#define OM_NSTG   3
#define OM_STG_SZ 20480            // A 4K | B 16K
#define OM_DSM    (OM_NSTG*OM_STG_SZ)   // 61440

__global__ __launch_bounds__(512) void offmask_mma_kernel(
    const float* __restrict__ x,
    const float* __restrict__ b_off, const float* __restrict__ b_mask)
{
    extern __shared__ char dsm[];
    const uint32_t u_stg = smem_u32(dsm);

    const int tid  = threadIdx.x;
    const int wid  = tid >> 5;
    const int lane = tid & 31;
    const int h0   = blockIdx.x * 2;
    const int b    = blockIdx.y;
    const float* xb = x + (size_t)b*CIN*HH*WW;

    if (wid < 8){
        // ---------------- PRODUCERS ----------------
        const int p  = tid & 127;
        const int cg = tid >> 7;
        const int hh = p >> 6, wp = p & 63;
        const int prow = p*128;
        const int psw  = p & 7;

        for (int s = 0; s < 18; s++){
            const int st = s % OM_NSTG;
            if (s >= OM_NSTG) BAR_SYNC(4 + st, 512);
            const uint32_t uc = u_stg + (uint32_t)st*OM_STG_SZ;

            // A tile: 32 o x 64 c fp16
            {
                const __half* src = g_wOM + (size_t)s*32*64;
                int o = tid >> 3, q = tid & 7;
                uint32_t dst = uc + (uint32_t)(o*128 + ((q ^ (o & 7)) << 4));
                CP_ASYNC16(dst, src + (size_t)o*64 + q*8);
                CP_COMMIT();
            }

            // B tile: shifted window of x (NCHW scalar, coalesced)
            {
                const int half = (s >= 9);
                const int ntap = s - half*9;
                const int ky = ntap / 3, kx = ntap - ky*3;
                const int y  = h0 + hh - 1 + ky;
                const int xc = wp - 1 + kx;
                const bool valid = ((unsigned)y < 64u) & ((unsigned)xc < 64u);
                const float* src = xb + ((size_t)(half*64 + cg*32))*(HH*WW) + y*WW + xc;
                char* bufB = dsm + st*OM_STG_SZ + 4096;
                #pragma unroll
                for (int g = 0; g < 4; g++){
                    uint32_t hv[4];
                    #pragma unroll
                    for (int e = 0; e < 4; e++){
                        int c0 = g*8 + e*2;
                        float v0 = valid ? src[(size_t)c0*(HH*WW)]     : 0.f;
                        float v1 = valid ? src[(size_t)(c0+1)*(HH*WW)] : 0.f;
                        hv[e] = pack_h2(v0, v1);
                    }
                    uint32_t off = prow + (uint32_t)(((cg*4 + g) ^ psw) << 4);
                    *(uint4*)(bufB + off) = make_uint4(hv[0], hv[1], hv[2], hv[3]);
                }
            }
            CP_WAIT0();
            BAR_ARRIVE(1 + st, 512);
        }
    } else {
        // ---------------- CONSUMERS ----------------
        const int wn = wid - 8;
        const int ar  = (lane & 7) + (((lane >> 3) & 1) << 3);
        const int akh = (lane >> 4) & 1;
        const int br  = (lane & 7) + (((lane >> 4) & 1) << 3);
        const int bkh = (lane >> 3) & 1;

        float acc[2][2][4];
        #pragma unroll
        for (int a = 0; a < 2; a++)
            #pragma unroll
            for (int f = 0; f < 2; f++)
                #pragma unroll
                for (int e = 0; e < 4; e++) acc[a][f][e] = 0.f;

        for (int s = 0; s < 18; s++){
            const int st = s % OM_NSTG;
            BAR_SYNC(1 + st, 512);
            const uint32_t sA = u_stg + (uint32_t)st*OM_STG_SZ;
            const uint32_t sB = sA + 4096;
            #pragma unroll
            for (int ks = 0; ks < 4; ks++){
                uint32_t a0[4], a1[4];
                {
                    int ca = ks*2 + akh;
                    int o0 = ar, o1 = ar + 16;
                    LDMX4(a0, sA + (uint32_t)(o0*128 + ((ca ^ (o0 & 7)) << 4)));
                    LDMX4(a1, sA + (uint32_t)(o1*128 + ((ca ^ (o1 & 7)) << 4)));
                }
                const int cb = ks*2 + bkh;
                const int pr = wn*16 + br;
                uint32_t th[4];
                LDMX4(th, sB + (uint32_t)(pr*128 + ((cb ^ (pr & 7)) << 4)));
                #pragma unroll
                for (int sub = 0; sub < 2; sub++){
                    MMA16816(acc[0][sub], a0[0],a0[1],a0[2],a0[3], th[2*sub], th[2*sub+1]);
                    MMA16816(acc[1][sub], a1[0],a1[1],a1[2],a1[3], th[2*sub], th[2*sub+1]);
                }
            }
            if (s < 18 - OM_NSTG) BAR_ARRIVE(4 + st, 512);
        }

        // ---- epilogue: bias, sigmoid(mask), write g_offmask ----
        #pragma unroll
        for (int mf = 0; mf < 2; mf++){
            #pragma unroll
            for (int sub = 0; sub < 2; sub++){
                #pragma unroll
                for (int e = 0; e < 4; e++){
                    int o  = mf*16 + (lane >> 2) + ((e >> 1) << 3);
                    int px = wn*16 + sub*8 + 2*(lane & 3) + (e & 1);
                    if (o < 27){
                        float v = acc[mf][sub][e];
                        if (o < 18) v += b_off[o];
                        else        v = 1.f/(1.f + __expf(-(v + b_mask[o-18])));
                        int hh = px >> 6, w = px & 63;
                        g_offmask[(((size_t)b*27 + o)*HH + h0 + hh)*WW + w] = v;
                    }
                }
            }
        }
    }
}

// ---------------------------------------------------------------------------
// Kernel 2: deform gather (fp32 NCHW, R9-proven) + mma.sync fp16.
// 768 threads: 8 producer warps + 16 consumer warps (16o x 64px tiles each,
// 32 acc regs -> ~85 regs/thread -> 24 warps/SM). 3-stage ring.
// Block = (b, 2 h-rows): D[128 o][128 px], K=1152 in 18 half-major stages.
// ---------------------------------------------------------------------------
#define N_STAGE  3
#define OFF_WT   0                       // 4*1152 floats  = 18432 B
#define OFF_AI   18432                   // 4*1152 int16   =  9216 B
#define OFF_STG  27648                   // stages
#define STG_SZ   32768                   // A 16K | B 16K
#define DSM_BYTES (OFF_STG + N_STAGE*STG_SZ)   // 125952
#define NTHR 768

__device__ __forceinline__ void gather_stage(
    char* bufB, const float* xb,
    const float* s_wt, const short* s_ai, int n_tap, int half, int ptid)
{
    const int p  = ptid & 127;
    const int cg = ptid >> 7;
    const int ci = n_tap*128 + p;
    const float w00 = s_wt[ci],      w01 = s_wt[1152+ci];
    const float w10 = s_wt[2304+ci], w11 = s_wt[3456+ci];
    const int a00 = s_ai[ci],      a01 = s_ai[1152+ci];
    const int a10 = s_ai[2304+ci], a11 = s_ai[3456+ci];
    const float* xp = xb + (size_t)(half*64 + cg*32)*(HH*WW);
    const int prow = p*128;
    const int psw  = p & 7;

    #pragma unroll
    for (int g = 0; g < 4; g++){
        uint32_t hv[4];
        #pragma unroll
        for (int e = 0; e < 4; e++){
            const float* xc0 = xp + (size_t)(g*8 + e*2)*(HH*WW);
            const float* xc1 = xc0 + HH*WW;
            float v0 = w00*xc0[a00] + w01*xc0[a01] + w10*xc0[a10] + w11*xc0[a11];
            float v1 = w00*xc1[a00] + w01*xc1[a01] + w10*xc1[a10] + w11*xc1[a11];
            hv[e] = pack_h2(v0, v1);
        }
        int chunk = cg*4 + g;
        uint32_t off = prow + (uint32_t)((chunk ^ psw) << 4);
        *(uint4*)(bufB + off) = make_uint4(hv[0], hv[1], hv[2], hv[3]);
    }
}

__device__ __forceinline__ void cpasync_A(uint32_t bufA_u32, int stage_s, int ptid)
{
    const __half* src = g_wA + (size_t)stage_s*128*64;
    #pragma unroll
    for (int r = 0; r < 4; r++){
        int id = r*256 + ptid;
        int o = id >> 3, q = id & 7;
        uint32_t dst = bufA_u32 + (uint32_t)(o*128 + ((q ^ (o & 7)) << 4));
        CP_ASYNC16(dst, src + (size_t)o*64 + q*8);
    }
}

// Consumer: 16 warps, warp tile = 16 o x 64 px
__device__ __forceinline__ void mma_stage16(
    uint32_t sA, uint32_t sB, float acc[8][4], int om, int wn, int lane)
{
    const int ar  = (lane & 7) + (((lane >> 3) & 1) << 3);
    const int akh = (lane >> 4) & 1;
    const int o0  = om*16 + ar;
    const int br  = (lane & 7) + (((lane >> 4) & 1) << 3);
    const int bkh = (lane >> 3) & 1;

    #pragma unroll
    for (int ks = 0; ks < 4; ks++){
        uint32_t a0[4];
        {
            int ca = ks*2 + akh;
            LDMX4(a0, sA + (uint32_t)(o0*128 + ((ca ^ (o0 & 7)) << 4)));
        }
        const int cb = ks*2 + bkh;
        #pragma unroll
        for (int g = 0; g < 4; g++){
            int pr = wn*64 + g*16 + br;
            uint32_t th[4];
            LDMX4(th, sB + (uint32_t)(pr*128 + ((cb ^ (pr & 7)) << 4)));
            #pragma unroll
            for (int sub = 0; sub < 2; sub++){
                MMA16816(acc[g*2+sub], a0[0],a0[1],a0[2],a0[3], th[2*sub], th[2*sub+1]);
            }
        }
    }
}

__global__ __launch_bounds__(NTHR, 1) void deform_kernel(
    const float* __restrict__ x, float* __restrict__ out)
{
    extern __shared__ char dsm[];
    float* s_wt = (float*)(dsm + OFF_WT);
    short* s_ai = (short*)(dsm + OFF_AI);
    const uint32_t u_base = smem_u32(dsm);
    const uint32_t u_stg  = u_base + OFF_STG;

    const int tid  = threadIdx.x;
    const int wid  = tid >> 5;
    const int lane = tid & 31;
    const int h0   = blockIdx.x * 2;
    const int b    = blockIdx.y;

    const float* om_ = g_offmask + (size_t)b*27*HH*WW;
    for (int i = tid; i < 1152; i += NTHR){
        int n = i >> 7, rr = i & 127;
        int hh = rr >> 6, p = rr & 63;
        int h_ = h0 + hh;
        float offy = om_[((size_t)(2*n  )*HH + h_)*WW + p];
        float offx = om_[((size_t)(2*n+1)*HH + h_)*WW + p];
        float m    = om_[((size_t)(18+n )*HH + h_)*WW + p];
        float py = offy + (float)(h_ - 1 + n/3);
        float px = offx + (float)(p  - 1 + n%3);
        float fy = floorf(py), fx = floorf(px);
        int y0 = (int)fy, x0 = (int)fx;
        float ly = py - fy, lx = px - fx;
        float hy = 1.f - ly, hx = 1.f - lx;
        int y1 = y0 + 1, x1 = x0 + 1;
        float vy0 = ((unsigned)y0 < 64u) ? 1.f : 0.f;
        float vy1 = ((unsigned)y1 < 64u) ? 1.f : 0.f;
        float vx0 = ((unsigned)x0 < 64u) ? 1.f : 0.f;
        float vx1 = ((unsigned)x1 < 64u) ? 1.f : 0.f;
        int y0c = min(max(y0,0),63), y1c = min(max(y1,0),63);
        int x0c = min(max(x0,0),63), x1c = min(max(x1,0),63);
        s_wt[0*1152 + i] = m*hy*hx*vy0*vx0;
        s_wt[1*1152 + i] = m*hy*lx*vy0*vx1;
        s_wt[2*1152 + i] = m*ly*hx*vy1*vx0;
        s_wt[3*1152 + i] = m*ly*lx*vy1*vx1;
        s_ai[0*1152 + i] = (short)(y0c*WW + x0c);
        s_ai[1*1152 + i] = (short)(y0c*WW + x1c);
        s_ai[2*1152 + i] = (short)(y1c*WW + x0c);
        s_ai[3*1152 + i] = (short)(y1c*WW + x1c);
    }
    __syncthreads();

    const float* xb = x + (size_t)b*CIN*HH*WW;

    if (wid < 8){
        // ================= PRODUCERS (warps 0-7) =================
        const int ptid = tid;           // 0..255
        for (int s = 0; s < 18; s++){
            const int st = s % N_STAGE;
            if (s >= N_STAGE) BAR_SYNC(4 + st, NTHR);       // wait empty
            const uint32_t uc = u_stg + (uint32_t)st*STG_SZ;
            cpasync_A(uc, s, ptid);
            CP_COMMIT();
            const int half = (s >= 9);
            const int ntap = s - half*9;
            gather_stage(dsm + OFF_STG + st*STG_SZ + 16384, xb, s_wt, s_ai,
                         ntap, half, ptid);
            CP_WAIT0();
            BAR_ARRIVE(1 + st, NTHR);                       // signal full
        }
    } else {
        // ================= CONSUMERS (warps 8-23) =================
        const int cwid = wid - 8;       // 0..15
        const int om   = cwid & 7;      // o-frag: rows om*16..om*16+15
        const int wn   = cwid >> 3;     // px half: 0/1

        float acc[8][4];
        #pragma unroll
        for (int f = 0; f < 8; f++)
            #pragma unroll
            for (int e = 0; e < 4; e++) acc[f][e] = 0.f;

        for (int s = 0; s < 18; s++){
            const int st = s % N_STAGE;
            BAR_SYNC(1 + st, NTHR);                          // wait full
            const uint32_t uc = u_stg + (uint32_t)st*STG_SZ;
            mma_stage16(uc, uc + 16384, acc, om, wn, lane);
            if (s < 18 - N_STAGE) BAR_ARRIVE(4 + st, NTHR);  // signal empty
        }

        // ---- epilogue: warp tile 16o x 64px -> out[b][o][h0+wn][w] ----
        const int h_ = h0 + wn;
        const int o  = om*16 + (lane >> 2);
        float* p0 = out + (((size_t)b*COUT + o    )*HH + h_)*WW;
        float* p1 = out + (((size_t)b*COUT + o + 8)*HH + h_)*WW;
        #pragma unroll
        for (int nf = 0; nf < 8; nf++){
            int w = nf*8 + 2*(lane & 3);
            *(float2*)(p0 + w) = make_float2(acc[nf][0], acc[nf][1]);
            *(float2*)(p1 + w) = make_float2(acc[nf][2], acc[nf][3]);
        }
    }
}

// ---------------------------------------------------------------------------
extern "C" void kernel_launch(void* const* d_in, const int* in_sizes, int n_in,
                              void* d_out, int out_size)
{
    const float* x      = (const float*)d_in[0];
    const float* w_conv = (const float*)d_in[1];
    const float* w_off  = (const float*)d_in[2];
    const float* b_off  = (const float*)d_in[3];
    const float* w_mask = (const float*)d_in[4];
    const float* b_mask = (const float*)d_in[5];
    float* out = (float*)d_out;

    cudaFuncSetAttribute(offmask_mma_kernel,
                         cudaFuncAttributeMaxDynamicSharedMemorySize, OM_DSM);
    cudaFuncSetAttribute(deform_kernel,
                         cudaFuncAttributeMaxDynamicSharedMemorySize, DSM_BYTES);

    prep_w_kernel<<<(18*128*64 + 255)/256, 256>>>(w_conv, w_off, w_mask);
    offmask_mma_kernel<<<dim3(32, 16), 512, OM_DSM>>>(x, b_off, b_mask);
    deform_kernel<<<dim3(32, 16), NTHR, DSM_BYTES>>>(x, out);
}

// round 14
// speedup vs baseline: 1.1092x; 1.1092x over previous
#include <cuda_runtime.h>
#include <cuda_fp16.h>
#include <cstdint>

#define BATCH 16
#define CIN   128
#define COUT  128
#define HH    64
#define WW    64

// ---------------------------------------------------------------------------
// Scratch (device globals: allocation-free rule)
// ---------------------------------------------------------------------------
__device__ float g_offmask[(size_t)BATCH*27*HH*WW]; // [b][27][h][w]
// Column-pair array: g_xph[c_plane][y*64+xc] = (x[y][xc], xc<63 ? x[y][xc+1] : 0) fp16
__device__ __half2 g_xph[(size_t)BATCH*CIN*HH*WW];
// Main-conv weights fp16, layout [stage s = half*9 + tap][o:128][k:64]
__device__ __half g_wA[18*128*64];
// Offset/mask-conv weights fp16, layout [stage][o:32 (27 used)][k:64]
__device__ __half g_wOM[18*32*64];

typedef unsigned long long ull;

// ---------------------------------------------------------------------------
// Helpers
// ---------------------------------------------------------------------------
__device__ __forceinline__ uint32_t smem_u32(const void* p){
    uint32_t a;
    asm("{ .reg .u64 t; cvta.to.shared.u64 t, %1; cvt.u32.u64 %0, t; }" : "=r"(a) : "l"(p));
    return a;
}

#define LDMX4(r, addr) \
    asm volatile("ldmatrix.sync.aligned.m8n8.x4.shared.b16 {%0,%1,%2,%3}, [%4];" \
        : "=r"((r)[0]), "=r"((r)[1]), "=r"((r)[2]), "=r"((r)[3]) : "r"(addr))

#define MMA16816(d, a0, a1, a2, a3, b0, b1) \
    asm volatile("mma.sync.aligned.m16n8k16.row.col.f32.f16.f16.f32 " \
        "{%0,%1,%2,%3}, {%4,%5,%6,%7}, {%8,%9}, {%0,%1,%2,%3};" \
        : "+f"((d)[0]), "+f"((d)[1]), "+f"((d)[2]), "+f"((d)[3]) \
        : "r"(a0), "r"(a1), "r"(a2), "r"(a3), "r"(b0), "r"(b1))

#define CP_ASYNC16(dst, src) \
    asm volatile("cp.async.ca.shared.global [%0], [%1], 16;" :: "r"(dst), "l"(src))
#define CP_COMMIT()  asm volatile("cp.async.commit_group;" ::: "memory")
#define CP_WAIT0()   asm volatile("cp.async.wait_group 0;" ::: "memory")

// Named-barrier producer/consumer sync (512 threads)
#define BAR_SYNC(id)   asm volatile("bar.sync %0, 512;"   :: "r"(id) : "memory")
#define BAR_ARRIVE(id) asm volatile("bar.arrive %0, 512;" :: "r"(id) : "memory")

__device__ __forceinline__ uint32_t pack_h2(float v0, float v1){
    __half h0 = __float2half_rn(v0);
    __half h1 = __float2half_rn(v1);
    return ((uint32_t)__half_as_ushort(h1) << 16) | __half_as_ushort(h0);
}

// ---------------------------------------------------------------------------
// Kernel A: build column-pair array from x (NCHW fp32)
// ---------------------------------------------------------------------------
__global__ __launch_bounds__(256) void xpair_kernel(const float* __restrict__ x){
    size_t i = (size_t)blockIdx.x * 256 + threadIdx.x;
    if (i < (size_t)BATCH*CIN*HH*WW){
        int xc = (int)(i & 63);
        float v0 = x[i];
        float v1 = (xc < 63) ? x[i+1] : 0.f;
        g_xph[i] = __floats2half2_rn(v0, v1);
    }
}

// ---------------------------------------------------------------------------
// Kernel 0: prep fp16 weight tiles for both GEMMs
// ---------------------------------------------------------------------------
__global__ void prep_w_kernel(const float* __restrict__ w_conv,
                              const float* __restrict__ w_off,
                              const float* __restrict__ w_mask){
    int i = blockIdx.x * blockDim.x + threadIdx.x;
    if (i < 18*128*64){
        int n = i / (128*128);
        int o = (i >> 7) & 127;
        int c = i & 127;
        float w = w_conv[((size_t)o*128 + c)*9 + n];
        int s = (c >> 6)*9 + n;
        size_t di = ((size_t)s*128 + o)*64 + (c & 63);
        g_wA[di] = __float2half_rn(w);
    }
    if (i < 18*32*64){
        int s  = i >> 11;
        int o  = (i >> 6) & 31;
        int cl = i & 63;
        int half = s / 9, n = s - half*9;
        int c = half*64 + cl;
        float w = 0.f;
        if (o < 18)      w = w_off [((size_t)o*128 + c)*9 + n];
        else if (o < 27) w = w_mask[((size_t)(o-18)*128 + c)*9 + n];
        g_wOM[i] = __float2half_rn(w);
    }
}

// ---------------------------------------------------------------------------
// Kernel 1: offset+mask conv as fp16 MMA, warp-specialized (proven R9 version)
// Block = (b, 2 h-rows): D[32 oc][128 px], K=1152 in 18 half-major stages.
// ---------------------------------------------------------------------------
#define OM_NSTG   3
#define OM_STG_SZ 20480            // A 4K | B 16K
#define OM_DSM    (OM_NSTG*OM_STG_SZ)   // 61440

__global__ __launch_bounds__(512) void offmask_mma_kernel(
    const float* __restrict__ x,
    const float* __restrict__ b_off, const float* __restrict__ b_mask)
{
    extern __shared__ char dsm[];
    const uint32_t u_stg = smem_u32(dsm);

    const int tid  = threadIdx.x;
    const int wid  = tid >> 5;
    const int lane = tid & 31;
    const int h0   = blockIdx.x * 2;
    const int b    = blockIdx.y;
    const float* xb = x + (size_t)b*CIN*HH*WW;

    if (wid < 8){
        // ---------------- PRODUCERS ----------------
        const int p  = tid & 127;
        const int cg = tid >> 7;
        const int hh = p >> 6, wp = p & 63;
        const int prow = p*128;
        const int psw  = p & 7;

        for (int s = 0; s < 18; s++){
            const int st = s % OM_NSTG;
            if (s >= OM_NSTG) BAR_SYNC(4 + st);
            const uint32_t uc = u_stg + (uint32_t)st*OM_STG_SZ;

            // A tile: 32 o x 64 c fp16
            {
                const __half* src = g_wOM + (size_t)s*32*64;
                int o = tid >> 3, q = tid & 7;
                uint32_t dst = uc + (uint32_t)(o*128 + ((q ^ (o & 7)) << 4));
                CP_ASYNC16(dst, src + (size_t)o*64 + q*8);
                CP_COMMIT();
            }

            // B tile: shifted window of x (NCHW scalar, coalesced)
            {
                const int half = (s >= 9);
                const int ntap = s - half*9;
                const int ky = ntap / 3, kx = ntap - ky*3;
                const int y  = h0 + hh - 1 + ky;
                const int xc = wp - 1 + kx;
                const bool valid = ((unsigned)y < 64u) & ((unsigned)xc < 64u);
                const float* src = xb + ((size_t)(half*64 + cg*32))*(HH*WW) + y*WW + xc;
                char* bufB = dsm + st*OM_STG_SZ + 4096;
                #pragma unroll
                for (int g = 0; g < 4; g++){
                    uint32_t hv[4];
                    #pragma unroll
                    for (int e = 0; e < 4; e++){
                        int c0 = g*8 + e*2;
                        float v0 = valid ? src[(size_t)c0*(HH*WW)]     : 0.f;
                        float v1 = valid ? src[(size_t)(c0+1)*(HH*WW)] : 0.f;
                        hv[e] = pack_h2(v0, v1);
                    }
                    uint32_t off = prow + (uint32_t)(((cg*4 + g) ^ psw) << 4);
                    *(uint4*)(bufB + off) = make_uint4(hv[0], hv[1], hv[2], hv[3]);
                }
            }
            CP_WAIT0();
            BAR_ARRIVE(1 + st);
        }
    } else {
        // ---------------- CONSUMERS ----------------
        const int wn = wid - 8;
        const int ar  = (lane & 7) + (((lane >> 3) & 1) << 3);
        const int akh = (lane >> 4) & 1;
        const int br  = (lane & 7) + (((lane >> 4) & 1) << 3);
        const int bkh = (lane >> 3) & 1;

        float acc[2][2][4];
        #pragma unroll
        for (int a = 0; a < 2; a++)
            #pragma unroll
            for (int f = 0; f < 2; f++)
                #pragma unroll
                for (int e = 0; e < 4; e++) acc[a][f][e] = 0.f;

        for (int s = 0; s < 18; s++){
            const int st = s % OM_NSTG;
            BAR_SYNC(1 + st);
            const uint32_t sA = u_stg + (uint32_t)st*OM_STG_SZ;
            const uint32_t sB = sA + 4096;
            #pragma unroll
            for (int ks = 0; ks < 4; ks++){
                uint32_t a0[4], a1[4];
                {
                    int ca = ks*2 + akh;
                    int o0 = ar, o1 = ar + 16;
                    LDMX4(a0, sA + (uint32_t)(o0*128 + ((ca ^ (o0 & 7)) << 4)));
                    LDMX4(a1, sA + (uint32_t)(o1*128 + ((ca ^ (o1 & 7)) << 4)));
                }
                const int cb = ks*2 + bkh;
                const int pr = wn*16 + br;
                uint32_t th[4];
                LDMX4(th, sB + (uint32_t)(pr*128 + ((cb ^ (pr & 7)) << 4)));
                #pragma unroll
                for (int sub = 0; sub < 2; sub++){
                    MMA16816(acc[0][sub], a0[0],a0[1],a0[2],a0[3], th[2*sub], th[2*sub+1]);
                    MMA16816(acc[1][sub], a1[0],a1[1],a1[2],a1[3], th[2*sub], th[2*sub+1]);
                }
            }
            if (s < 18 - OM_NSTG) BAR_ARRIVE(4 + st);
        }

        // ---- epilogue: bias, sigmoid(mask), write g_offmask ----
        #pragma unroll
        for (int mf = 0; mf < 2; mf++){
            #pragma unroll
            for (int sub = 0; sub < 2; sub++){
                #pragma unroll
                for (int e = 0; e < 4; e++){
                    int o  = mf*16 + (lane >> 2) + ((e >> 1) << 3);
                    int px = wn*16 + sub*8 + 2*(lane & 3) + (e & 1);
                    if (o < 27){
                        float v = acc[mf][sub][e];
                        if (o < 18) v += b_off[o];
                        else        v = 1.f/(1.f + __expf(-(v + b_mask[o-18])));
                        int hh = px >> 6, w = px & 63;
                        g_offmask[(((size_t)b*27 + o)*HH + h0 + hh)*WW + w] = v;
                    }
                }
            }
        }
    }
}

// ---------------------------------------------------------------------------
// Kernel 2: deform gather (pair loads from g_xph) + mma.sync fp16.
// 512 threads: 8 producer + 8 consumer warps (R9-proven structure).
// 3-stage ring, half-major K order. Per-channel gather = 2 x LDG.32 (half2).
// Block = (b, 2 h-rows): D[128 o][128 px], K=1152 in 18 stages of 64.
// ---------------------------------------------------------------------------
#define N_STAGE  3
#define OFF_WT   0                       // 4*1152 floats  = 18432 B
#define OFF_AI   18432                   // 2*1152 int16   =  4608 B
#define OFF_STG  23040                   // stages
#define STG_SZ   32768                   // A 16K | B 16K
#define DSM_BYTES (OFF_STG + N_STAGE*STG_SZ)   // 121344

__device__ __forceinline__ void gather_stage(
    char* bufB, const __half2* xphb,
    const float* s_wt, const short* s_ai, int n_tap, int half, int ptid)
{
    const int p  = ptid & 127;
    const int cg = ptid >> 7;
    const int ci = n_tap*128 + p;
    const float w0L = s_wt[ci],      w0H = s_wt[1152+ci];
    const float w1L = s_wt[2304+ci], w1H = s_wt[3456+ci];
    const int a0 = s_ai[ci];
    const int a1 = s_ai[1152+ci];
    const __half2* xp = xphb + (size_t)(half*64 + cg*32)*(HH*WW);
    const int prow = p*128;
    const int psw  = p & 7;

    #pragma unroll
    for (int g = 0; g < 4; g++){        // 8 channels per g
        uint32_t hv[4];
        #pragma unroll
        for (int e = 0; e < 4; e++){
            const __half2* c0 = xp + (size_t)(g*8 + e*2)*(HH*WW);
            const __half2* c1 = c0 + HH*WW;
            float2 r00 = __half22float2(c0[a0]);
            float2 r01 = __half22float2(c0[a1]);
            float2 r10 = __half22float2(c1[a0]);
            float2 r11 = __half22float2(c1[a1]);
            float v0 = w0L*r00.x + w0H*r00.y + w1L*r01.x + w1H*r01.y;
            float v1 = w0L*r10.x + w0H*r10.y + w1L*r11.x + w1H*r11.y;
            hv[e] = pack_h2(v0, v1);
        }
        int chunk = cg*4 + g;
        uint32_t off = prow + (uint32_t)((chunk ^ psw) << 4);
        *(uint4*)(bufB + off) = make_uint4(hv[0], hv[1], hv[2], hv[3]);
    }
}

__device__ __forceinline__ void cpasync_A(uint32_t bufA_u32, int stage_s, int ptid)
{
    const __half* src = g_wA + (size_t)stage_s*128*64;
    #pragma unroll
    for (int r = 0; r < 4; r++){
        int id = r*256 + ptid;
        int o = id >> 3, q = id & 7;
        uint32_t dst = bufA_u32 + (uint32_t)(o*128 + ((q ^ (o & 7)) << 4));
        CP_ASYNC16(dst, src + (size_t)o*64 + q*8);
    }
}

__device__ __forceinline__ void mma_stage(
    uint32_t sA, uint32_t sB, float acc[2][8][4], int wm, int wn, int lane)
{
    const int ar  = (lane & 7) + (((lane >> 3) & 1) << 3);
    const int akh = (lane >> 4) & 1;
    const int o0  = wm*32 + ar;
    const int o1  = o0 + 16;
    const int br  = (lane & 7) + (((lane >> 4) & 1) << 3);
    const int bkh = (lane >> 3) & 1;

    #pragma unroll
    for (int ks = 0; ks < 4; ks++){
        uint32_t a0[4], a1[4];
        {
            int ca = ks*2 + akh;
            LDMX4(a0, sA + (uint32_t)(o0*128 + ((ca ^ (o0 & 7)) << 4)));
            LDMX4(a1, sA + (uint32_t)(o1*128 + ((ca ^ (o1 & 7)) << 4)));
        }
        const int cb = ks*2 + bkh;
        #pragma unroll
        for (int g = 0; g < 4; g++){
            int pr = wn*64 + g*16 + br;
            uint32_t th[4];
            LDMX4(th, sB + (uint32_t)(pr*128 + ((cb ^ (pr & 7)) << 4)));
            #pragma unroll
            for (int sub = 0; sub < 2; sub++){
                int nf = g*2 + sub;
                MMA16816(acc[0][nf], a0[0],a0[1],a0[2],a0[3], th[2*sub], th[2*sub+1]);
                MMA16816(acc[1][nf], a1[0],a1[1],a1[2],a1[3], th[2*sub], th[2*sub+1]);
            }
        }
    }
}

__global__ __launch_bounds__(512) void deform_kernel(float* __restrict__ out)
{
    extern __shared__ char dsm[];
    float* s_wt = (float*)(dsm + OFF_WT);
    short* s_ai = (short*)(dsm + OFF_AI);
    const uint32_t u_base = smem_u32(dsm);
    const uint32_t u_stg  = u_base + OFF_STG;

    const int tid  = threadIdx.x;
    const int wid  = tid >> 5;
    const int lane = tid & 31;
    const int h0   = blockIdx.x * 2;
    const int b    = blockIdx.y;

    // ---- corner-pair tables for all (tap n, px) ----
    const float* om = g_offmask + (size_t)b*27*HH*WW;
    for (int i = tid; i < 1152; i += 512){
        int n = i >> 7, rr = i & 127;
        int hh = rr >> 6, p = rr & 63;
        int h_ = h0 + hh;
        float offy = om[((size_t)(2*n  )*HH + h_)*WW + p];
        float offx = om[((size_t)(2*n+1)*HH + h_)*WW + p];
        float m    = om[((size_t)(18+n )*HH + h_)*WW + p];
        float py = offy + (float)(h_ - 1 + n/3);
        float px = offx + (float)(p  - 1 + n%3);
        float fy = floorf(py), fx = floorf(px);
        int y0 = (int)fy, x0 = (int)fx;
        float ly = py - fy, lx = px - fx;
        float hy = 1.f - ly, hx = 1.f - lx;
        float vy0 = ((unsigned)y0     < 64u) ? 1.f : 0.f;
        float vy1 = ((unsigned)(y0+1) < 64u) ? 1.f : 0.f;
        int y0c = min(max(y0,0),63), y1c = min(max(y0+1,0),63);
        // column pair weights (lo = col xA, hi = col xA+1 with zero-pad at 63)
        float wLo, wHi;
        if ((unsigned)x0 < 64u){
            float vx1 = ((unsigned)(x0+1) < 64u) ? 1.f : 0.f;
            wLo = hx; wHi = lx*vx1;
        } else if (x0 == -1){
            wLo = lx; wHi = 0.f;
        } else {
            wLo = 0.f; wHi = 0.f;
        }
        int xA = min(max(x0,0),63);
        s_wt[0*1152 + i] = m*hy*vy0*wLo;
        s_wt[1*1152 + i] = m*hy*vy0*wHi;
        s_wt[2*1152 + i] = m*ly*vy1*wLo;
        s_wt[3*1152 + i] = m*ly*vy1*wHi;
        s_ai[0*1152 + i] = (short)(y0c*WW + xA);
        s_ai[1*1152 + i] = (short)(y1c*WW + xA);
    }
    __syncthreads();

    const __half2* xphb = g_xph + (size_t)b*CIN*HH*WW;

    if (wid < 8){
        // ================= PRODUCERS (warps 0-7) =================
        const int ptid = tid;
        for (int s = 0; s < 18; s++){
            const int st = s % N_STAGE;
            if (s >= N_STAGE) BAR_SYNC(4 + st);
            const uint32_t uc = u_stg + (uint32_t)st*STG_SZ;
            cpasync_A(uc, s, ptid);
            CP_COMMIT();
            const int half = (s >= 9);
            const int ntap = s - half*9;
            gather_stage(dsm + OFF_STG + st*STG_SZ + 16384, xphb, s_wt, s_ai,
                         ntap, half, ptid);
            CP_WAIT0();
            BAR_ARRIVE(1 + st);
        }
    } else {
        // ================= CONSUMERS (warps 8-15) =================
        const int cwid = wid - 8;
        const int wm   = cwid & 3;
        const int wn   = cwid >> 2;

        float acc[2][8][4];
        #pragma unroll
        for (int a = 0; a < 2; a++)
            #pragma unroll
            for (int f = 0; f < 8; f++)
                #pragma unroll
                for (int e = 0; e < 4; e++) acc[a][f][e] = 0.f;

        for (int s = 0; s < 18; s++){
            const int st = s % N_STAGE;
            BAR_SYNC(1 + st);
            const uint32_t uc = u_stg + (uint32_t)st*STG_SZ;
            mma_stage(uc, uc + 16384, acc, wm, wn, lane);
            if (s < 18 - N_STAGE) BAR_ARRIVE(4 + st);
        }

        const int h_ = h0 + wn;
        #pragma unroll
        for (int mf = 0; mf < 2; mf++){
            int o = wm*32 + mf*16 + (lane >> 2);
            float* p0 = out + (((size_t)b*COUT + o    )*HH + h_)*WW;
            float* p1 = out + (((size_t)b*COUT + o + 8)*HH + h_)*WW;
            #pragma unroll
            for (int nf = 0; nf < 8; nf++){
                int w = nf*8 + 2*(lane & 3);
                *(float2*)(p0 + w) = make_float2(acc[mf][nf][0], acc[mf][nf][1]);
                *(float2*)(p1 + w) = make_float2(acc[mf][nf][2], acc[mf][nf][3]);
            }
        }
    }
}

// ---------------------------------------------------------------------------
extern "C" void kernel_launch(void* const* d_in, const int* in_sizes, int n_in,
                              void* d_out, int out_size)
{
    const float* x      = (const float*)d_in[0];
    const float* w_conv = (const float*)d_in[1];
    const float* w_off  = (const float*)d_in[2];
    const float* b_off  = (const float*)d_in[3];
    const float* w_mask = (const float*)d_in[4];
    const float* b_mask = (const float*)d_in[5];
    float* out = (float*)d_out;

    cudaFuncSetAttribute(offmask_mma_kernel,
                         cudaFuncAttributeMaxDynamicSharedMemorySize, OM_DSM);
    cudaFuncSetAttribute(deform_kernel,
                         cudaFuncAttributeMaxDynamicSharedMemorySize, DSM_BYTES);

    xpair_kernel<<<(BATCH*CIN*HH*WW + 255)/256, 256>>>(x);
    prep_w_kernel<<<(18*128*64 + 255)/256, 256>>>(w_conv, w_off, w_mask);
    offmask_mma_kernel<<<dim3(32, 16), 512, OM_DSM>>>(x, b_off, b_mask);
    deform_kernel<<<dim3(32, 16), 512, DSM_BYTES>>>(out);
}

// round 15
// speedup vs baseline: 1.3006x; 1.1725x over previous
#include <cuda_runtime.h>
#include <cuda_fp16.h>
#include <cstdint>

#define BATCH 16
#define CIN   128
#define COUT  128
#define HH    64
#define WW    64

// ---------------------------------------------------------------------------
// Scratch (device globals: allocation-free rule)
// ---------------------------------------------------------------------------
__device__ float g_offmask[(size_t)BATCH*27*HH*WW]; // [b][27][h][w]
// Column-pair array: g_xph[c_plane][y*64+xc] = (x[y][xc], xc<63 ? x[y][xc+1] : 0) fp16
__device__ __half2 g_xph[(size_t)BATCH*CIN*HH*WW];
// Main-conv weights fp16, layout [stage s = half*9 + tap][o:128][k:64]
__device__ __half g_wA[18*128*64];
// Offset/mask-conv weights fp16, layout [stage][o:32 (27 used)][k:64]
__device__ __half g_wOM[18*32*64];

typedef unsigned long long ull;

// ---------------------------------------------------------------------------
// Helpers
// ---------------------------------------------------------------------------
__device__ __forceinline__ uint32_t smem_u32(const void* p){
    uint32_t a;
    asm("{ .reg .u64 t; cvta.to.shared.u64 t, %1; cvt.u32.u64 %0, t; }" : "=r"(a) : "l"(p));
    return a;
}

#define LDMX4(r, addr) \
    asm volatile("ldmatrix.sync.aligned.m8n8.x4.shared.b16 {%0,%1,%2,%3}, [%4];" \
        : "=r"((r)[0]), "=r"((r)[1]), "=r"((r)[2]), "=r"((r)[3]) : "r"(addr))

#define MMA16816(d, a0, a1, a2, a3, b0, b1) \
    asm volatile("mma.sync.aligned.m16n8k16.row.col.f32.f16.f16.f32 " \
        "{%0,%1,%2,%3}, {%4,%5,%6,%7}, {%8,%9}, {%0,%1,%2,%3};" \
        : "+f"((d)[0]), "+f"((d)[1]), "+f"((d)[2]), "+f"((d)[3]) \
        : "r"(a0), "r"(a1), "r"(a2), "r"(a3), "r"(b0), "r"(b1))

#define CP_ASYNC16(dst, src) \
    asm volatile("cp.async.ca.shared.global [%0], [%1], 16;" :: "r"(dst), "l"(src))
#define CP_COMMIT()  asm volatile("cp.async.commit_group;" ::: "memory")
#define CP_WAIT0()   asm volatile("cp.async.wait_group 0;" ::: "memory")

// Named-barrier producer/consumer sync, parameterized participant count
#define BAR_SYNC(id, cnt)   asm volatile("bar.sync %0, %1;"   :: "r"(id), "r"(cnt) : "memory")
#define BAR_ARRIVE(id, cnt) asm volatile("bar.arrive %0, %1;" :: "r"(id), "r"(cnt) : "memory")

__device__ __forceinline__ uint32_t pack_h2(float v0, float v1){
    __half h0 = __float2half_rn(v0);
    __half h1 = __float2half_rn(v1);
    return ((uint32_t)__half_as_ushort(h1) << 16) | __half_as_ushort(h0);
}

// ---------------------------------------------------------------------------
// Kernel 0: xpair build + fp16 weight prep, fused into one launch.
// blocks [0,8192): g_xph (4 elems/thread); blocks [8192,8768): weight tiles.
// ---------------------------------------------------------------------------
__global__ __launch_bounds__(256) void prep_all_kernel(
    const float* __restrict__ x, const float* __restrict__ w_conv,
    const float* __restrict__ w_off, const float* __restrict__ w_mask)
{
    const int bid = blockIdx.x;
    if (bid < 8192){
        size_t base = (size_t)bid*1024 + (size_t)threadIdx.x*4;
        #pragma unroll
        for (int e = 0; e < 4; e++){
            size_t i = base + e;
            int xc = (int)(i & 63);
            float v0 = x[i];
            float v1 = (xc < 63) ? x[i+1] : 0.f;
            g_xph[i] = __floats2half2_rn(v0, v1);
        }
    } else {
        int i = (bid - 8192)*256 + threadIdx.x;
        if (i < 18*128*64){
            int n = i / (128*128);
            int o = (i >> 7) & 127;
            int c = i & 127;
            float w = w_conv[((size_t)o*128 + c)*9 + n];
            int s = (c >> 6)*9 + n;
            size_t di = ((size_t)s*128 + o)*64 + (c & 63);
            g_wA[di] = __float2half_rn(w);
        }
        if (i < 18*32*64){
            int s  = i >> 11;
            int o  = (i >> 6) & 31;
            int cl = i & 63;
            int half = s / 9, n = s - half*9;
            int c = half*64 + cl;
            float w = 0.f;
            if (o < 18)      w = w_off [((size_t)o*128 + c)*9 + n];
            else if (o < 27) w = w_mask[((size_t)(o-18)*128 + c)*9 + n];
            g_wOM[i] = __float2half_rn(w);
        }
    }
}

// ---------------------------------------------------------------------------
// Kernel 1: offset+mask conv as fp16 MMA, warp-specialized (proven R9 version)
// Block = (b, 2 h-rows): D[32 oc][128 px], K=1152 in 18 half-major stages.
// ---------------------------------------------------------------------------
#define OM_NSTG   3
#define OM_STG_SZ 20480            // A 4K | B 16K
#define OM_DSM    (OM_NSTG*OM_STG_SZ)   // 61440

__global__ __launch_bounds__(512) void offmask_mma_kernel(
    const float* __restrict__ x,
    const float* __restrict__ b_off, const float* __restrict__ b_mask)
{
    extern __shared__ char dsm[];
    const uint32_t u_stg = smem_u32(dsm);

    const int tid  = threadIdx.x;
    const int wid  = tid >> 5;
    const int lane = tid & 31;
    const int h0   = blockIdx.x * 2;
    const int b    = blockIdx.y;
    const float* xb = x + (size_t)b*CIN*HH*WW;

    if (wid < 8){
        // ---------------- PRODUCERS ----------------
        const int p  = tid & 127;
        const int cg = tid >> 7;
        const int hh = p >> 6, wp = p & 63;
        const int prow = p*128;
        const int psw  = p & 7;

        for (int s = 0; s < 18; s++){
            const int st = s % OM_NSTG;
            if (s >= OM_NSTG) BAR_SYNC(4 + st, 512);
            const uint32_t uc = u_stg + (uint32_t)st*OM_STG_SZ;

            // A tile: 32 o x 64 c fp16
            {
                const __half* src = g_wOM + (size_t)s*32*64;
                int o = tid >> 3, q = tid & 7;
                uint32_t dst = uc + (uint32_t)(o*128 + ((q ^ (o & 7)) << 4));
                CP_ASYNC16(dst, src + (size_t)o*64 + q*8);
                CP_COMMIT();
            }

            // B tile: shifted window of x (NCHW scalar, coalesced)
            {
                const int half = (s >= 9);
                const int ntap = s - half*9;
                const int ky = ntap / 3, kx = ntap - ky*3;
                const int y  = h0 + hh - 1 + ky;
                const int xc = wp - 1 + kx;
                const bool valid = ((unsigned)y < 64u) & ((unsigned)xc < 64u);
                const float* src = xb + ((size_t)(half*64 + cg*32))*(HH*WW) + y*WW + xc;
                char* bufB = dsm + st*OM_STG_SZ + 4096;
                #pragma unroll
                for (int g = 0; g < 4; g++){
                    uint32_t hv[4];
                    #pragma unroll
                    for (int e = 0; e < 4; e++){
                        int c0 = g*8 + e*2;
                        float v0 = valid ? src[(size_t)c0*(HH*WW)]     : 0.f;
                        float v1 = valid ? src[(size_t)(c0+1)*(HH*WW)] : 0.f;
                        hv[e] = pack_h2(v0, v1);
                    }
                    uint32_t off = prow + (uint32_t)(((cg*4 + g) ^ psw) << 4);
                    *(uint4*)(bufB + off) = make_uint4(hv[0], hv[1], hv[2], hv[3]);
                }
            }
            CP_WAIT0();
            BAR_ARRIVE(1 + st, 512);
        }
    } else {
        // ---------------- CONSUMERS ----------------
        const int wn = wid - 8;
        const int ar  = (lane & 7) + (((lane >> 3) & 1) << 3);
        const int akh = (lane >> 4) & 1;
        const int br  = (lane & 7) + (((lane >> 4) & 1) << 3);
        const int bkh = (lane >> 3) & 1;

        float acc[2][2][4];
        #pragma unroll
        for (int a = 0; a < 2; a++)
            #pragma unroll
            for (int f = 0; f < 2; f++)
                #pragma unroll
                for (int e = 0; e < 4; e++) acc[a][f][e] = 0.f;

        for (int s = 0; s < 18; s++){
            const int st = s % OM_NSTG;
            BAR_SYNC(1 + st, 512);
            const uint32_t sA = u_stg + (uint32_t)st*OM_STG_SZ;
            const uint32_t sB = sA + 4096;
            #pragma unroll
            for (int ks = 0; ks < 4; ks++){
                uint32_t a0[4], a1[4];
                {
                    int ca = ks*2 + akh;
                    int o0 = ar, o1 = ar + 16;
                    LDMX4(a0, sA + (uint32_t)(o0*128 + ((ca ^ (o0 & 7)) << 4)));
                    LDMX4(a1, sA + (uint32_t)(o1*128 + ((ca ^ (o1 & 7)) << 4)));
                }
                const int cb = ks*2 + bkh;
                const int pr = wn*16 + br;
                uint32_t th[4];
                LDMX4(th, sB + (uint32_t)(pr*128 + ((cb ^ (pr & 7)) << 4)));
                #pragma unroll
                for (int sub = 0; sub < 2; sub++){
                    MMA16816(acc[0][sub], a0[0],a0[1],a0[2],a0[3], th[2*sub], th[2*sub+1]);
                    MMA16816(acc[1][sub], a1[0],a1[1],a1[2],a1[3], th[2*sub], th[2*sub+1]);
                }
            }
            if (s < 18 - OM_NSTG) BAR_ARRIVE(4 + st, 512);
        }

        // ---- epilogue: bias, sigmoid(mask), write g_offmask ----
        #pragma unroll
        for (int mf = 0; mf < 2; mf++){
            #pragma unroll
            for (int sub = 0; sub < 2; sub++){
                #pragma unroll
                for (int e = 0; e < 4; e++){
                    int o  = mf*16 + (lane >> 2) + ((e >> 1) << 3);
                    int px = wn*16 + sub*8 + 2*(lane & 3) + (e & 1);
                    if (o < 27){
                        float v = acc[mf][sub][e];
                        if (o < 18) v += b_off[o];
                        else        v = 1.f/(1.f + __expf(-(v + b_mask[o-18])));
                        int hh = px >> 6, w = px & 63;
                        g_offmask[(((size_t)b*27 + o)*HH + h0 + hh)*WW + w] = v;
                    }
                }
            }
        }
    }
}

// ---------------------------------------------------------------------------
// Kernel 2: deform, 256-thread CTA covering ONE h-row (2 CTAs/SM -> 32 warps).
// Warps 0-3 produce (pair gather from g_xph + cp.async A), warps 4-7 consume.
// Block = (b, h): D[128 o][64 px], K=1152 in 18 half-major stages of 64.
// ---------------------------------------------------------------------------
#define N_STAGE  3
#define OFF_WT   0                       // 4*576 floats = 9216 B
#define OFF_AI   9216                    // 2*576 int16  = 2304 B
#define OFF_STG  11520                   // stages (128-aligned)
#define STG_SZ   24576                   // A 16K | B 8K
#define DSM_BYTES (OFF_STG + N_STAGE*STG_SZ)   // 85248
#define NTHR 256

__device__ __forceinline__ void gather_stage(
    char* bufB, const __half2* xphb,
    const float* s_wt, const short* s_ai, int n_tap, int half, int ptid)
{
    const int p  = ptid & 63;
    const int cg = ptid >> 6;           // 0/1: 32-ch half of the 64
    const int ci = n_tap*64 + p;
    const float w0L = s_wt[ci],      w0H = s_wt[576+ci];
    const float w1L = s_wt[1152+ci], w1H = s_wt[1728+ci];
    const int a0 = s_ai[ci];
    const int a1 = s_ai[576+ci];
    const __half2* xp = xphb + (size_t)(half*64 + cg*32)*(HH*WW);
    const int prow = p*128;
    const int psw  = p & 7;

    #pragma unroll
    for (int g = 0; g < 4; g++){        // 8 channels per g
        uint32_t hv[4];
        #pragma unroll
        for (int e = 0; e < 4; e++){
            const __half2* c0 = xp + (size_t)(g*8 + e*2)*(HH*WW);
            const __half2* c1 = c0 + HH*WW;
            float2 r00 = __half22float2(c0[a0]);
            float2 r01 = __half22float2(c0[a1]);
            float2 r10 = __half22float2(c1[a0]);
            float2 r11 = __half22float2(c1[a1]);
            float v0 = w0L*r00.x + w0H*r00.y + w1L*r01.x + w1H*r01.y;
            float v1 = w0L*r10.x + w0H*r10.y + w1L*r11.x + w1H*r11.y;
            hv[e] = pack_h2(v0, v1);
        }
        int chunk = cg*4 + g;
        uint32_t off = prow + (uint32_t)((chunk ^ psw) << 4);
        *(uint4*)(bufB + off) = make_uint4(hv[0], hv[1], hv[2], hv[3]);
    }
}

__device__ __forceinline__ void cpasync_A(uint32_t bufA_u32, int stage_s, int ptid)
{
    const __half* src = g_wA + (size_t)stage_s*128*64;
    #pragma unroll
    for (int r = 0; r < 8; r++){
        int id = r*128 + ptid;          // 0..1023
        int o = id >> 3, q = id & 7;
        uint32_t dst = bufA_u32 + (uint32_t)(o*128 + ((q ^ (o & 7)) << 4));
        CP_ASYNC16(dst, src + (size_t)o*64 + q*8);
    }
}

// Consumer warp tile: 32 o x 64 px
__device__ __forceinline__ void mma_stage(
    uint32_t sA, uint32_t sB, float acc[2][8][4], int wm, int lane)
{
    const int ar  = (lane & 7) + (((lane >> 3) & 1) << 3);
    const int akh = (lane >> 4) & 1;
    const int o0  = wm*32 + ar;
    const int o1  = o0 + 16;
    const int br  = (lane & 7) + (((lane >> 4) & 1) << 3);
    const int bkh = (lane >> 3) & 1;

    #pragma unroll
    for (int ks = 0; ks < 4; ks++){
        uint32_t a0[4], a1[4];
        {
            int ca = ks*2 + akh;
            LDMX4(a0, sA + (uint32_t)(o0*128 + ((ca ^ (o0 & 7)) << 4)));
            LDMX4(a1, sA + (uint32_t)(o1*128 + ((ca ^ (o1 & 7)) << 4)));
        }
        const int cb = ks*2 + bkh;
        #pragma unroll
        for (int g = 0; g < 4; g++){
            int pr = g*16 + br;
            uint32_t th[4];
            LDMX4(th, sB + (uint32_t)(pr*128 + ((cb ^ (pr & 7)) << 4)));
            #pragma unroll
            for (int sub = 0; sub < 2; sub++){
                int nf = g*2 + sub;
                MMA16816(acc[0][nf], a0[0],a0[1],a0[2],a0[3], th[2*sub], th[2*sub+1]);
                MMA16816(acc[1][nf], a1[0],a1[1],a1[2],a1[3], th[2*sub], th[2*sub+1]);
            }
        }
    }
}

__global__ __launch_bounds__(NTHR, 2) void deform_kernel(float* __restrict__ out)
{
    extern __shared__ char dsm[];
    float* s_wt = (float*)(dsm + OFF_WT);
    short* s_ai = (short*)(dsm + OFF_AI);
    const uint32_t u_base = smem_u32(dsm);
    const uint32_t u_stg  = u_base + OFF_STG;

    const int tid  = threadIdx.x;
    const int wid  = tid >> 5;
    const int lane = tid & 31;
    const int h    = blockIdx.x;
    const int b    = blockIdx.y;

    // ---- corner-pair tables for (tap n, px p), single h-row ----
    const float* om = g_offmask + (size_t)b*27*HH*WW;
    for (int i = tid; i < 576; i += NTHR){
        int n = i >> 6, p = i & 63;
        float offy = om[((size_t)(2*n  )*HH + h)*WW + p];
        float offx = om[((size_t)(2*n+1)*HH + h)*WW + p];
        float m    = om[((size_t)(18+n )*HH + h)*WW + p];
        float py = offy + (float)(h - 1 + n/3);
        float px = offx + (float)(p - 1 + n%3);
        float fy = floorf(py), fx = floorf(px);
        int y0 = (int)fy, x0 = (int)fx;
        float ly = py - fy, lx = px - fx;
        float hy = 1.f - ly, hx = 1.f - lx;
        float vy0 = ((unsigned)y0     < 64u) ? 1.f : 0.f;
        float vy1 = ((unsigned)(y0+1) < 64u) ? 1.f : 0.f;
        int y0c = min(max(y0,0),63), y1c = min(max(y0+1,0),63);
        float wLo, wHi;
        if ((unsigned)x0 < 64u){
            float vx1 = ((unsigned)(x0+1) < 64u) ? 1.f : 0.f;
            wLo = hx; wHi = lx*vx1;
        } else if (x0 == -1){
            wLo = lx; wHi = 0.f;
        } else {
            wLo = 0.f; wHi = 0.f;
        }
        int xA = min(max(x0,0),63);
        s_wt[0*576 + i] = m*hy*vy0*wLo;
        s_wt[1*576 + i] = m*hy*vy0*wHi;
        s_wt[2*576 + i] = m*ly*vy1*wLo;
        s_wt[3*576 + i] = m*ly*vy1*wHi;
        s_ai[0*576 + i] = (short)(y0c*WW + xA);
        s_ai[1*576 + i] = (short)(y1c*WW + xA);
    }
    __syncthreads();

    const __half2* xphb = g_xph + (size_t)b*CIN*HH*WW;

    if (wid < 4){
        // ================= PRODUCERS (warps 0-3) =================
        const int ptid = tid;           // 0..127
        for (int s = 0; s < 18; s++){
            const int st = s % N_STAGE;
            if (s >= N_STAGE) BAR_SYNC(4 + st, NTHR);       // wait empty
            const uint32_t uc = u_stg + (uint32_t)st*STG_SZ;
            cpasync_A(uc, s, ptid);
            CP_COMMIT();
            const int half = (s >= 9);
            const int ntap = s - half*9;
            gather_stage(dsm + OFF_STG + st*STG_SZ + 16384, xphb, s_wt, s_ai,
                         ntap, half, ptid);
            CP_WAIT0();
            BAR_ARRIVE(1 + st, NTHR);                       // signal full
        }
    } else {
        // ================= CONSUMERS (warps 4-7) =================
        const int wm = wid - 4;         // o-block: rows wm*32 .. +31

        float acc[2][8][4];
        #pragma unroll
        for (int a = 0; a < 2; a++)
            #pragma unroll
            for (int f = 0; f < 8; f++)
                #pragma unroll
                for (int e = 0; e < 4; e++) acc[a][f][e] = 0.f;

        for (int s = 0; s < 18; s++){
            const int st = s % N_STAGE;
            BAR_SYNC(1 + st, NTHR);                          // wait full
            const uint32_t uc = u_stg + (uint32_t)st*STG_SZ;
            mma_stage(uc, uc + 16384, acc, wm, lane);
            if (s < 18 - N_STAGE) BAR_ARRIVE(4 + st, NTHR);  // signal empty
        }

        // ---- epilogue: warp tile 32o x 64px -> out[b][o][h][w] ----
        #pragma unroll
        for (int mf = 0; mf < 2; mf++){
            int o = wm*32 + mf*16 + (lane >> 2);
            float* p0 = out + (((size_t)b*COUT + o    )*HH + h)*WW;
            float* p1 = out + (((size_t)b*COUT + o + 8)*HH + h)*WW;
            #pragma unroll
            for (int nf = 0; nf < 8; nf++){
                int w = nf*8 + 2*(lane & 3);
                *(float2*)(p0 + w) = make_float2(acc[mf][nf][0], acc[mf][nf][1]);
                *(float2*)(p1 + w) = make_float2(acc[mf][nf][2], acc[mf][nf][3]);
            }
        }
    }
}

// ---------------------------------------------------------------------------
extern "C" void kernel_launch(void* const* d_in, const int* in_sizes, int n_in,
                              void* d_out, int out_size)
{
    const float* x      = (const float*)d_in[0];
    const float* w_conv = (const float*)d_in[1];
    const float* w_off  = (const float*)d_in[2];
    const float* b_off  = (const float*)d_in[3];
    const float* w_mask = (const float*)d_in[4];
    const float* b_mask = (const float*)d_in[5];
    float* out = (float*)d_out;

    cudaFuncSetAttribute(offmask_mma_kernel,
                         cudaFuncAttributeMaxDynamicSharedMemorySize, OM_DSM);
    cudaFuncSetAttribute(deform_kernel,
                         cudaFuncAttributeMaxDynamicSharedMemorySize, DSM_BYTES);

    prep_all_kernel<<<8192 + 576, 256>>>(x, w_conv, w_off, w_mask);
    offmask_mma_kernel<<<dim3(32, 16), 512, OM_DSM>>>(x, b_off, b_mask);
    deform_kernel<<<dim3(64, 16), NTHR, DSM_BYTES>>>(out);
}